// round 11
// baseline (speedup 1.0000x reference)
#include <cuda_runtime.h>
#include <cuda_fp16.h>
#include <cstdint>

#define BT 2048
#define NF 128
#define CC 256

// Device globals (no allocations)
__device__ float    g_Wct[CC * CC];          // Wc = Wg @ Wv (fp32 temp)
__device__ uint32_t g_WqkPh[CC * CC / 2];    // fragment-packed half2 B for phase 1
__device__ uint32_t g_WctPh[CC * CC / 2];    // fragment-packed half2 B for phase 4
__device__ float    g_bc[CC];                // Wg @ bv + bg

__device__ __forceinline__ uint32_t pk(float a, float b) {
    __half2 h = __floats2half2_rn(a, b);
    return *(uint32_t*)&h;
}
__device__ __forceinline__ uint32_t smem_u32(const void* p) {
    uint32_t a;
    asm("{ .reg .u64 t; cvta.to.shared.u64 t, %1; cvt.u32.u64 %0, t; }" : "=r"(a) : "l"(p));
    return a;
}
#define CP16(d, s) asm volatile("cp.async.ca.shared.global [%0], [%1], 16;" :: "r"(d), "l"(s) : "memory")
#define CP_COMMIT() asm volatile("cp.async.commit_group;" ::: "memory")
#define WAITG3()    asm volatile("cp.async.wait_group 3;" ::: "memory")

__device__ __forceinline__ void mma16(float c[4], uint4 a, uint32_t b0, uint32_t b1) {
    asm volatile(
        "mma.sync.aligned.m16n8k16.row.col.f32.f16.f16.f32 "
        "{%0,%1,%2,%3},{%4,%5,%6,%7},{%8,%9},{%0,%1,%2,%3};"
        : "+f"(c[0]), "+f"(c[1]), "+f"(c[2]), "+f"(c[3])
        : "r"(a.x), "r"(a.y), "r"(a.z), "r"(a.w), "r"(b0), "r"(b1));
}

// A-pack word index, 32-row slabs (m16n8k16 row fragment order).
__device__ __forceinline__ int a_w(int S, int m, int k) {
    int slab = m >> 5, mt = (m >> 4) & 1, h = (m >> 3) & 1, g = m & 7;
    int s = k >> 4, kk = k & 15, t = (kk & 7) >> 1, hi = kk >> 3;
    return (((slab * S + s) * 2 + mt) * 32 + g * 4 + t) * 4 + h + 2 * hi;
}
// B-pack word index: b0=(k=2t|2t+1, n) b1=(k+8 pair); 8-n groups
__device__ __forceinline__ int b_w(int NP, int k, int n) {
    int s = k >> 4, kk = k & 15, t = (kk & 7) >> 1, hi = kk >> 3;
    return ((s * NP + (n >> 3)) * 32 + (n & 7) * 4 + t) * 2 + hi;
}

// One k16 step: warp tile 32 x (NT*8). A mt stride 128 words, B nt stride 64 words.
template <int NT>
__device__ __forceinline__ void step16(float (&acc)[2][8][4], const uint32_t* __restrict__ Aw,
                                       const uint32_t* __restrict__ Bw) {
    uint4 af[2];
#pragma unroll
    for (int mt = 0; mt < 2; mt++) af[mt] = *(const uint4*)(Aw + mt * 128);
#pragma unroll
    for (int nt = 0; nt < NT; nt++) {
        uint2 bf = *(const uint2*)(Bw + nt * 64);
#pragma unroll
        for (int mt = 0; mt < 2; mt++) mma16(acc[mt][nt], af[mt], bf.x, bf.y);
    }
}

// ---------------- prep 1: Wc = Wg @ Wv, bc = Wg @ bv + bg ----------------
__global__ void prep_wc(const float* __restrict__ Wg, const float* __restrict__ Wv,
                        const float* __restrict__ bv, const float* __restrict__ bg)
{
    __shared__ float sWg[CC];
    __shared__ float sred[CC];
    const int i = blockIdx.x, j = threadIdx.x;
    const float wg = Wg[i * CC + j];
    sWg[j] = wg;
    __syncthreads();
    float a0 = 0.f, a1 = 0.f, a2 = 0.f, a3 = 0.f;
#pragma unroll 8
    for (int k = 0; k < CC; k += 4) {
        a0 = fmaf(sWg[k + 0], Wv[(k + 0) * CC + j], a0);
        a1 = fmaf(sWg[k + 1], Wv[(k + 1) * CC + j], a1);
        a2 = fmaf(sWg[k + 2], Wv[(k + 2) * CC + j], a2);
        a3 = fmaf(sWg[k + 3], Wv[(k + 3) * CC + j], a3);
    }
    g_Wct[i * CC + j] = (a0 + a1) + (a2 + a3);
    sred[j] = wg * bv[j];
    __syncthreads();
    for (int s = 128; s > 0; s >>= 1) {
        if (j < s) sred[j] += sred[j + s];
        __syncthreads();
    }
    if (j == 0) g_bc[i] = sred[0] + bg[i];
}

// ---------------- prep 2: fragment-pack half2 weights (B(k,n) = W[n][k]) ----------------
__global__ void prep_pack(const float* __restrict__ Wq, const float* __restrict__ Wk)
{
    const int k = 2 * blockIdx.x, n = threadIdx.x;
    float q0, q1;
    if (n < 128) { q0 = Wq[n * CC + k]; q1 = Wq[n * CC + k + 1]; }
    else         { q0 = Wk[(n - 128) * CC + k]; q1 = Wk[(n - 128) * CC + k + 1]; }
    const int wi = b_w(32, k, n);
    g_WqkPh[wi] = pk(q0, q1);
    g_WctPh[wi] = pk(g_Wct[n * CC + k], g_Wct[n * CC + k + 1]);
}

// SMEM word map: scr[1024] | A1[16384] (xe -> Q|Kt -> attn|Kt -> ax)
//              | BW[32768] (16 warps x 4-deep x 512-word private B ring; also phase-3 x bufs)
constexpr int OFF_SCR = 0;
constexpr int OFF_A   = 1024;
constexpr int OFF_K   = OFF_A + 8192;
constexpr int OFF_BW  = OFF_A + 16384;
constexpr int SMEM_W  = OFF_BW + 32768;      // 50176 words
constexpr int SMEM_BYTES = SMEM_W * 4;       // 200704 B

__global__ void __launch_bounds__(512, 1)
fused_kernel(const float* __restrict__ x, const float* __restrict__ ee,
             const float* __restrict__ adj, const float* __restrict__ alpha_p,
             const float* __restrict__ bq, const float* __restrict__ bk,
             const float* __restrict__ gamma, const float* __restrict__ beta,
             float* __restrict__ out)
{
    extern __shared__ uint32_t smw[];
    float*    scr = (float*)(smw + OFF_SCR);
    uint32_t* A1  = smw + OFF_A;     // xe-pack (S=16) / ax-pack (S=16)
    uint32_t* QW  = smw + OFF_A;     // Q-pack (S=8) then attn-pack
    uint32_t* KtW = smw + OFF_K;     // Kt-pack (NP=16)
    uint32_t* BW  = smw + OFF_BW;
    const uint32_t bwu = smem_u32(smw + OFF_BW);

    const int tid = threadIdx.x;
    const int w = tid >> 5, lane = tid & 31;
    const int g = lane >> 2, t = lane & 3;
    const int wm = w >> 2, wn = w & 3;          // 4 x 4 warp grid
    const int mrow = wm * 32;
    const int ncol = wn * 64;                   // phases 1,3,4 (N=256)
    const int ncol2 = wn * 32;                  // phase 2 (N=128)
    const int b = blockIdx.x;
    const float* xb = x + (size_t)b * (NF * CC);

    float acc[2][8][4];

    // Warp-private self-load: warp w copies its own wn-slice (512 words) of chunk c
    // into its private ring buffer. Lane l copies words [l*16, l*16+16) -> bytes d+0,16,32,48.
#define ISSUE_SELF(c, gW) do { \
    if ((c) < 16) { \
        uint32_t d = bwu + (w * 2048 + ((c) & 3) * 512 + lane * 16) * 4; \
        const uint32_t* s_ = (gW) + (c) * 2048 + wn * 512 + lane * 16; \
        CP16(d, s_); CP16(d + 16, s_ + 4); CP16(d + 32, s_ + 8); CP16(d + 48, s_ + 12); \
    } \
    CP_COMMIT(); \
} while (0)

    ISSUE_SELF(0, g_WqkPh); ISSUE_SELF(1, g_WqkPh);
    ISSUE_SELF(2, g_WqkPh); ISSUE_SELF(3, g_WqkPh);

    // ===== stage xe = fp16(x + ee) in A-pack (S=16) =====
#pragma unroll 4
    for (int j = 0; j < 16; j++) {
        int f = j * 512 + tid;
        int r = f >> 6, c0 = (f & 63) << 2;
        float4 v = __ldg((const float4*)(xb + r * 256 + c0));
        float4 e = __ldg((const float4*)(ee + r * 256 + c0));
        int w0 = a_w(16, r, c0);
        A1[w0]     = pk(v.x + e.x, v.y + e.y);
        A1[w0 + 4] = pk(v.z + e.z, v.w + e.w);
    }
    __syncthreads();   // xe visible to all warps

    // ===== Phase 1: [Q|K] = xe @ Wqk^T  (16 ksteps, barrier-free mainloop) =====
#pragma unroll
    for (int mt = 0; mt < 2; mt++)
#pragma unroll
        for (int nt = 0; nt < 8; nt++)
#pragma unroll
            for (int e = 0; e < 4; e++) acc[mt][nt][e] = 0.f;

    for (int c = 0; c < 16; c++) {
        WAITG3();
        __syncwarp();
        step16<8>(acc, A1 + wm * 4096 + c * 256 + lane * 4,
                  BW + w * 2048 + (c & 3) * 512 + lane * 2);
        ISSUE_SELF(c + 4, g_WqkPh);
    }
    __syncthreads();   // all xe reads done before Q/Kt overwrite A1

    // epilogue: Q-pack (wn<2, S=8) / Kt-pack (wn>=2, NP=16), +bias, fp16
#pragma unroll
    for (int nt = 0; nt < 8; nt++) {
        const int n = ncol + nt * 8 + 2 * t;
#pragma unroll
        for (int mt = 0; mt < 2; mt++) {
            const int r0 = mrow + mt * 16 + g, r1 = r0 + 8;
            if (wn < 2) {
                float2 bb = __ldg((const float2*)&bq[n]);
                QW[a_w(8, r0, n)] = pk(acc[mt][nt][0] + bb.x, acc[mt][nt][1] + bb.y);
                QW[a_w(8, r1, n)] = pk(acc[mt][nt][2] + bb.x, acc[mt][nt][3] + bb.y);
            } else {
                const int ck = n - 128;
                float2 bb = __ldg((const float2*)&bk[ck]);
                KtW[b_w(16, ck, r0)] = pk(acc[mt][nt][0] + bb.x, acc[mt][nt][1] + bb.y);
                KtW[b_w(16, ck, r1)] = pk(acc[mt][nt][2] + bb.x, acc[mt][nt][3] + bb.y);
            }
        }
    }
    __syncthreads();

    // ===== Phase 2: scores = Q @ K^T  (8 ksteps, N=128; warp tile 32x32) =====
#pragma unroll
    for (int mt = 0; mt < 2; mt++)
#pragma unroll
        for (int nt = 0; nt < 4; nt++)
#pragma unroll
            for (int e = 0; e < 4; e++) acc[mt][nt][e] = 0.f;
#pragma unroll
    for (int s = 0; s < 8; s++)
        step16<4>(acc, QW + wm * 2048 + s * 256 + lane * 4,
                  KtW + s * 1024 + wn * 256 + lane * 2);

    // ===== softmax(scores/sqrt(128) + fa*relu(adj)) -> attn-pack (overwrites Q) =====
    // max-subtraction omitted: |score| <~ 13 << 88, exp safe in fp32.
    {
        const float fa = __ldg(alpha_p);
        const float invs = 0.08838834764831845f;
#pragma unroll
        for (int mt = 0; mt < 2; mt++)
#pragma unroll
            for (int h = 0; h < 2; h++) {
                const int r = mrow + mt * 16 + g + h * 8;
                float s = 0.f;
#pragma unroll
                for (int nt = 0; nt < 4; nt++) {
                    const int col = ncol2 + nt * 8 + 2 * t;
                    float2 av = __ldg((const float2*)&adj[r * 128 + col]);
                    float p0 = __expf(acc[mt][nt][h * 2 + 0] * invs + fa * fmaxf(av.x, 0.f));
                    float p1 = __expf(acc[mt][nt][h * 2 + 1] * invs + fa * fmaxf(av.y, 0.f));
                    acc[mt][nt][h * 2 + 0] = p0;
                    acc[mt][nt][h * 2 + 1] = p1;
                    s += p0 + p1;
                }
                s += __shfl_xor_sync(0xffffffffu, s, 1);
                s += __shfl_xor_sync(0xffffffffu, s, 2);
                scr[r * 4 + wn] = s;
            }
        __syncthreads();
#pragma unroll
        for (int mt = 0; mt < 2; mt++)
#pragma unroll
            for (int h = 0; h < 2; h++) {
                const int r = mrow + mt * 16 + g + h * 8;
                const float inv = 1.f / (scr[r * 4] + scr[r * 4 + 1]
                                       + scr[r * 4 + 2] + scr[r * 4 + 3]);
#pragma unroll
                for (int nt = 0; nt < 4; nt++) {
                    const int col = ncol2 + nt * 8 + 2 * t;
                    QW[a_w(8, r, col)] = pk(acc[mt][nt][h * 2 + 0] * inv,
                                            acc[mt][nt][h * 2 + 1] * inv);
                }
            }
    }
    __syncthreads();   // attn visible before phase-3 reads

    // ===== Phase 3: ax = attn @ x  (4 chunks of 32 k-rows, double-buffered, 5 barriers) =====
#pragma unroll
    for (int mt = 0; mt < 2; mt++)
#pragma unroll
        for (int nt = 0; nt < 8; nt++)
#pragma unroll
            for (int e = 0; e < 4; e++) acc[mt][nt][e] = 0.f;

    // stage chunk 0
#pragma unroll
    for (int j = 0; j < 2; j++) {
        int idx = j * 512 + tid;
        int rp = idx >> 6, c4 = (idx & 63) << 2;
        float4 va = __ldg((const float4*)(xb + (2 * rp) * 256 + c4));
        float4 vb = __ldg((const float4*)(xb + (2 * rp + 1) * 256 + c4));
        const int sl = rp >> 3, tt = rp & 3, hi = (rp >> 2) & 1;
        const float ax4[4] = {va.x, va.y, va.z, va.w};
        const float bx4[4] = {vb.x, vb.y, vb.z, vb.w};
#pragma unroll
        for (int i = 0; i < 4; i++) {
            int n = c4 + i;
            BW[((sl * 32 + (n >> 3)) * 32 + (n & 7) * 4 + tt) * 2 + hi] = pk(ax4[i], bx4[i]);
        }
    }
    __syncthreads();

    for (int c = 0; c < 4; c++) {
        if (c < 3) {   // stage chunk c+1 into the other buffer
            uint32_t* buf = BW + ((c + 1) & 1) * 4096;
            const float* xs = xb + (c + 1) * 32 * 256;
#pragma unroll
            for (int j = 0; j < 2; j++) {
                int idx = j * 512 + tid;
                int rp = idx >> 6, c4 = (idx & 63) << 2;
                float4 va = __ldg((const float4*)(xs + (2 * rp) * 256 + c4));
                float4 vb = __ldg((const float4*)(xs + (2 * rp + 1) * 256 + c4));
                const int sl = rp >> 3, tt = rp & 3, hi = (rp >> 2) & 1;
                const float ax4[4] = {va.x, va.y, va.z, va.w};
                const float bx4[4] = {vb.x, vb.y, vb.z, vb.w};
#pragma unroll
                for (int i = 0; i < 4; i++) {
                    int n = c4 + i;
                    buf[((sl * 32 + (n >> 3)) * 32 + (n & 7) * 4 + tt) * 2 + hi] = pk(ax4[i], bx4[i]);
                }
            }
        }
        uint32_t* cur = BW + (c & 1) * 4096;
#pragma unroll
        for (int sl = 0; sl < 2; sl++)
            step16<8>(acc, QW + wm * 2048 + (c * 2 + sl) * 256 + lane * 4,
                      cur + sl * 2048 + wn * 512 + lane * 2);
        __syncthreads();
    }

    // prefetch first four weight chunks of phase 4 (BW ring free now)
    ISSUE_SELF(0, g_WctPh); ISSUE_SELF(1, g_WctPh);
    ISSUE_SELF(2, g_WctPh); ISSUE_SELF(3, g_WctPh);

    // epilogue: ax-pack (S=16) into A1 (attn/Kt dead)
#pragma unroll
    for (int nt = 0; nt < 8; nt++) {
        const int n = ncol + nt * 8 + 2 * t;
#pragma unroll
        for (int mt = 0; mt < 2; mt++) {
            const int r0 = mrow + mt * 16 + g, r1 = r0 + 8;
            A1[a_w(16, r0, n)] = pk(acc[mt][nt][0], acc[mt][nt][1]);
            A1[a_w(16, r1, n)] = pk(acc[mt][nt][2], acc[mt][nt][3]);
        }
    }
    __syncthreads();

    // ===== Phase 4: z = ax @ Wc^T  (16 ksteps, barrier-free mainloop) =====
#pragma unroll
    for (int mt = 0; mt < 2; mt++)
#pragma unroll
        for (int nt = 0; nt < 8; nt++)
#pragma unroll
            for (int e = 0; e < 4; e++) acc[mt][nt][e] = 0.f;

    for (int c = 0; c < 16; c++) {
        WAITG3();
        __syncwarp();
        step16<8>(acc, A1 + wm * 4096 + c * 256 + lane * 4,
                  BW + w * 2048 + (c & 3) * 512 + lane * 2);
        ISSUE_SELF(c + 4, g_WctPh);
    }

    // ===== LN epilogue: h = relu(z + bc) + x; LayerNorm over C; store =====
#pragma unroll
    for (int mt = 0; mt < 2; mt++)
#pragma unroll
        for (int h = 0; h < 2; h++) {
            const int r = mrow + mt * 16 + g + h * 8;
            float s1 = 0.f, s2 = 0.f;
#pragma unroll
            for (int nt = 0; nt < 8; nt++) {
                const int n = ncol + nt * 8 + 2 * t;
                float2 bc2 = __ldg((const float2*)&g_bc[n]);
                float2 xv = __ldg((const float2*)&xb[r * 256 + n]);
                float h0 = fmaxf(acc[mt][nt][h * 2 + 0] + bc2.x, 0.f) + xv.x;
                float h1 = fmaxf(acc[mt][nt][h * 2 + 1] + bc2.y, 0.f) + xv.y;
                acc[mt][nt][h * 2 + 0] = h0;
                acc[mt][nt][h * 2 + 1] = h1;
                s1 += h0 + h1;
                s2 += h0 * h0 + h1 * h1;
            }
            s1 += __shfl_xor_sync(0xffffffffu, s1, 1);
            s1 += __shfl_xor_sync(0xffffffffu, s1, 2);
            s2 += __shfl_xor_sync(0xffffffffu, s2, 1);
            s2 += __shfl_xor_sync(0xffffffffu, s2, 2);
            scr[r * 4 + wn] = s1;
            scr[512 + r * 4 + wn] = s2;
        }
    __syncthreads();
    float* ob = out + (size_t)b * (NF * CC);
#pragma unroll
    for (int mt = 0; mt < 2; mt++)
#pragma unroll
        for (int h = 0; h < 2; h++) {
            const int r = mrow + mt * 16 + g + h * 8;
            const float S  = scr[r * 4] + scr[r * 4 + 1] + scr[r * 4 + 2] + scr[r * 4 + 3];
            const float Q2 = scr[512 + r * 4] + scr[512 + r * 4 + 1]
                           + scr[512 + r * 4 + 2] + scr[512 + r * 4 + 3];
            const float mean = S * (1.f / 256.f);
            const float rstd = rsqrtf(Q2 * (1.f / 256.f) - mean * mean + 1e-5f);
#pragma unroll
            for (int nt = 0; nt < 8; nt++) {
                const int n = ncol + nt * 8 + 2 * t;
                float2 g2 = __ldg((const float2*)&gamma[n]);
                float2 b2 = __ldg((const float2*)&beta[n]);
                float2 o;
                o.x = (acc[mt][nt][h * 2 + 0] - mean) * rstd * g2.x + b2.x;
                o.y = (acc[mt][nt][h * 2 + 1] - mean) * rstd * g2.y + b2.y;
                *(float2*)(ob + r * 256 + n) = o;
            }
        }
#undef ISSUE_SELF
}

extern "C" void kernel_launch(void* const* d_in, const int* in_sizes, int n_in,
                              void* d_out, int out_size)
{
    (void)in_sizes; (void)n_in; (void)out_size;
    const float* x     = (const float*)d_in[0];
    const float* ee    = (const float*)d_in[1];
    const float* adj   = (const float*)d_in[2];
    const float* alpha = (const float*)d_in[3];
    const float* Wq    = (const float*)d_in[4];
    const float* bq    = (const float*)d_in[5];
    const float* Wk    = (const float*)d_in[6];
    const float* bk    = (const float*)d_in[7];
    const float* Wv    = (const float*)d_in[8];
    const float* bv    = (const float*)d_in[9];
    const float* Wg    = (const float*)d_in[10];
    const float* bg    = (const float*)d_in[11];
    const float* gamma = (const float*)d_in[12];
    const float* beta  = (const float*)d_in[13];
    float* out = (float*)d_out;

    cudaFuncSetAttribute(fused_kernel, cudaFuncAttributeMaxDynamicSharedMemorySize, SMEM_BYTES);
    prep_wc<<<CC, 256>>>(Wg, Wv, bv, bg);
    prep_pack<<<128, 256>>>(Wq, Wk);
    fused_kernel<<<BT, 512, SMEM_BYTES>>>(x, ee, adj, alpha, bq, bk, gamma, beta, out);
}

// round 12
// speedup vs baseline: 1.3646x; 1.3646x over previous
#include <cuda_runtime.h>
#include <cuda_fp16.h>
#include <cstdint>

#define BT 2048
#define NF 128
#define CC 256

// Device globals (no allocations)
__device__ uint32_t g_WqkPh[CC * CC / 2];    // fragment-packed half2 B for phase 1
__device__ uint32_t g_WctPh[CC * CC / 2];    // fragment-packed half2 B for phase 4
__device__ float    g_bc[CC];                // Wg @ bv + bg

__device__ __forceinline__ uint32_t pk(float a, float b) {
    __half2 h = __floats2half2_rn(a, b);
    return *(uint32_t*)&h;
}
__device__ __forceinline__ uint32_t smem_u32(const void* p) {
    uint32_t a;
    asm("{ .reg .u64 t; cvta.to.shared.u64 t, %1; cvt.u32.u64 %0, t; }" : "=r"(a) : "l"(p));
    return a;
}
#define CP16(d, s) asm volatile("cp.async.ca.shared.global [%0], [%1], 16;" :: "r"(d), "l"(s) : "memory")
#define CP_COMMIT() asm volatile("cp.async.commit_group;" ::: "memory")
#define CP_WAIT2()  asm volatile("cp.async.wait_group 2;" ::: "memory")

__device__ __forceinline__ void mma16(float c[4], uint4 a, uint32_t b0, uint32_t b1) {
    asm volatile(
        "mma.sync.aligned.m16n8k16.row.col.f32.f16.f16.f32 "
        "{%0,%1,%2,%3},{%4,%5,%6,%7},{%8,%9},{%0,%1,%2,%3};"
        : "+f"(c[0]), "+f"(c[1]), "+f"(c[2]), "+f"(c[3])
        : "r"(a.x), "r"(a.y), "r"(a.z), "r"(a.w), "r"(b0), "r"(b1));
}

// A-pack word index, 32-row slabs (m16n8k16 row fragment order).
__device__ __forceinline__ int a_w(int S, int m, int k) {
    int slab = m >> 5, mt = (m >> 4) & 1, h = (m >> 3) & 1, g = m & 7;
    int s = k >> 4, kk = k & 15, t = (kk & 7) >> 1, hi = kk >> 3;
    return (((slab * S + s) * 2 + mt) * 32 + g * 4 + t) * 4 + h + 2 * hi;
}
// B-pack word index: b0=(k=2t|2t+1, n) b1=(k+8 pair); 8-n groups
__device__ __forceinline__ int b_w(int NP, int k, int n) {
    int s = k >> 4, kk = k & 15, t = (kk & 7) >> 1, hi = kk >> 3;
    return ((s * NP + (n >> 3)) * 32 + (n & 7) * 4 + t) * 2 + hi;
}

// One k16 step: warp tile 32 x (NT*8). A mt stride 128 words, B nt stride 64 words.
template <int NT>
__device__ __forceinline__ void step16(float (&acc)[2][8][4], const uint32_t* __restrict__ Aw,
                                       const uint32_t* __restrict__ Bw) {
    uint4 af[2];
#pragma unroll
    for (int mt = 0; mt < 2; mt++) af[mt] = *(const uint4*)(Aw + mt * 128);
#pragma unroll
    for (int nt = 0; nt < NT; nt++) {
        uint2 bf = *(const uint2*)(Bw + nt * 64);
#pragma unroll
        for (int mt = 0; mt < 2; mt++) mma16(acc[mt][nt], af[mt], bf.x, bf.y);
    }
}

// ---------------- merged prep: Wct rows, bc, and both weight packs ----------------
__global__ void prep_all(const float* __restrict__ Wq, const float* __restrict__ Wk,
                         const float* __restrict__ Wg, const float* __restrict__ Wv,
                         const float* __restrict__ bv, const float* __restrict__ bg)
{
    __shared__ float sWg[8][256];
    __shared__ float sWct[8][260];
    __shared__ float part[8][8];
    const int bi = blockIdx.x;      // 0..31, owns Wct rows i0..i0+7
    const int j = threadIdx.x;      // 0..255
    const int i0 = bi * 8;
    const int w8 = j >> 5, lane = j & 31;

#pragma unroll
    for (int r = 0; r < 8; r++) sWg[r][j] = Wg[(i0 + r) * 256 + j];
    __syncthreads();

    float acc[8] = {0.f, 0.f, 0.f, 0.f, 0.f, 0.f, 0.f, 0.f};
#pragma unroll 4
    for (int k = 0; k < 256; k++) {
        float wv = Wv[k * 256 + j];
#pragma unroll
        for (int r = 0; r < 8; r++) acc[r] = fmaf(sWg[r][k], wv, acc[r]);
    }
#pragma unroll
    for (int r = 0; r < 8; r++) sWct[r][j] = acc[r];

#pragma unroll
    for (int r = 0; r < 8; r++) {
        float v = sWg[r][j] * bv[j];
#pragma unroll
        for (int off = 16; off; off >>= 1) v += __shfl_xor_sync(0xffffffffu, v, off);
        if (lane == 0) part[r][w8] = v;
    }
    __syncthreads();

    if (j < 8) {
        float s = 0.f;
#pragma unroll
        for (int ww = 0; ww < 8; ww++) s += part[j][ww];
        g_bc[i0 + j] = s + bg[i0 + j];
    }
    // pack Wct rows i0..i0+7 (1024 words, 4 per thread)
#pragma unroll
    for (int q = 0; q < 4; q++) {
        int idx = j * 4 + q;
        int nl = idx >> 7, kp = idx & 127;
        g_WctPh[b_w(32, 2 * kp, i0 + nl)] = pk(sWct[nl][2 * kp], sWct[nl][2 * kp + 1]);
    }
    // pack this block's 1/32 slice of Wqk (1024 (k-pair, n) pairs)
#pragma unroll
    for (int q = 0; q < 4; q++) {
        int p2 = bi * 1024 + j * 4 + q;
        int kp = p2 >> 8, n = p2 & 255;
        float q0, q1;
        if (n < 128) { q0 = Wq[n * 256 + 2 * kp]; q1 = Wq[n * 256 + 2 * kp + 1]; }
        else         { q0 = Wk[(n - 128) * 256 + 2 * kp]; q1 = Wk[(n - 128) * 256 + 2 * kp + 1]; }
        g_WqkPh[b_w(32, 2 * kp, n)] = pk(q0, q1);
    }
}

// SMEM word map: scr[1024] | A1[16384] (xe -> Q|Kt -> attn|Kt -> ax)
//              | BB[16384] (4 x 4096-word double-chunks; phase-3: 2 x 4096 x-bufs)
constexpr int OFF_SCR = 0;
constexpr int OFF_A   = 1024;
constexpr int OFF_K   = OFF_A + 8192;
constexpr int OFF_BB  = OFF_A + 16384;
constexpr int SMEM_W  = OFF_BB + 16384;      // 33792 words
constexpr int SMEM_BYTES = SMEM_W * 4;       // 135168 B

__global__ void __launch_bounds__(512, 1)
fused_kernel(const float* __restrict__ x, const float* __restrict__ ee,
             const float* __restrict__ adj, const float* __restrict__ alpha_p,
             const float* __restrict__ bq, const float* __restrict__ bk,
             const float* __restrict__ gamma, const float* __restrict__ beta,
             float* __restrict__ out)
{
    extern __shared__ uint32_t smw[];
    float*    scr = (float*)(smw + OFF_SCR);
    uint32_t* A1  = smw + OFF_A;     // xe-pack (S=16) / ax-pack (S=16)
    uint32_t* QW  = smw + OFF_A;     // Q-pack (S=8) then attn-pack
    uint32_t* KtW = smw + OFF_K;     // Kt-pack (NP=16)
    uint32_t* BB  = smw + OFF_BB;
    const uint32_t bbu = smem_u32(smw + OFF_BB);

    const int tid = threadIdx.x;
    const int w = tid >> 5, lane = tid & 31;
    const int g = lane >> 2, t = lane & 3;
    const int wm = w >> 2, wn = w & 3;          // 4 x 4 warp grid
    const int mrow = wm * 32;
    const int ncol = wn * 64;                   // phases 1,3,4 (N=256)
    const int ncol2 = wn * 32;                  // phase 2 (N=128)
    const int b = blockIdx.x;
    const float* xb = x + (size_t)b * (NF * CC);

    float acc[2][8][4];

    // double-chunk cc = ksteps {2cc, 2cc+1} = 4096 words; thread copies 8 words
#define ISSUE_W2(cc, gW) do { \
    if ((cc) < 8) { \
        uint32_t d = bbu + (((cc) & 3) * 4096 + tid * 8) * 4; \
        const uint32_t* s_ = (gW) + (cc) * 4096 + tid * 8; \
        CP16(d, s_); CP16(d + 16, s_ + 4); \
    } \
    CP_COMMIT(); \
} while (0)

    ISSUE_W2(0, g_WqkPh);
    ISSUE_W2(1, g_WqkPh);

    // ===== stage xe = fp16(x + ee) in A-pack (S=16) =====
#pragma unroll 4
    for (int j = 0; j < 16; j++) {
        int f = j * 512 + tid;
        int r = f >> 6, c0 = (f & 63) << 2;
        float4 v = __ldg((const float4*)(xb + r * 256 + c0));
        float4 e = __ldg((const float4*)(ee + r * 256 + c0));
        int w0 = a_w(16, r, c0);
        A1[w0]     = pk(v.x + e.x, v.y + e.y);
        A1[w0 + 4] = pk(v.z + e.z, v.w + e.w);
    }

    // ===== Phase 1: [Q|K] = xe @ Wqk^T  (8 double-ksteps, 8 barriers) =====
#pragma unroll
    for (int mt = 0; mt < 2; mt++)
#pragma unroll
        for (int nt = 0; nt < 8; nt++)
#pragma unroll
            for (int e = 0; e < 4; e++) acc[mt][nt][e] = 0.f;

    for (int cc = 0; cc < 8; cc++) {
        ISSUE_W2(cc + 2, g_WqkPh);
        CP_WAIT2();
        __syncthreads();
#pragma unroll
        for (int sl = 0; sl < 2; sl++)
            step16<8>(acc, A1 + wm * 4096 + (2 * cc + sl) * 256 + lane * 4,
                      BB + (cc & 3) * 4096 + sl * 2048 + wn * 512 + lane * 2);
    }
    __syncthreads();   // all xe reads done before Q/Kt overwrite A1

    // epilogue: Q-pack (wn<2, S=8) / Kt-pack (wn>=2, NP=16), +bias, fp16
#pragma unroll
    for (int nt = 0; nt < 8; nt++) {
        const int n = ncol + nt * 8 + 2 * t;
#pragma unroll
        for (int mt = 0; mt < 2; mt++) {
            const int r0 = mrow + mt * 16 + g, r1 = r0 + 8;
            if (wn < 2) {
                float2 bb = __ldg((const float2*)&bq[n]);
                QW[a_w(8, r0, n)] = pk(acc[mt][nt][0] + bb.x, acc[mt][nt][1] + bb.y);
                QW[a_w(8, r1, n)] = pk(acc[mt][nt][2] + bb.x, acc[mt][nt][3] + bb.y);
            } else {
                const int ck = n - 128;
                float2 bb = __ldg((const float2*)&bk[ck]);
                KtW[b_w(16, ck, r0)] = pk(acc[mt][nt][0] + bb.x, acc[mt][nt][1] + bb.y);
                KtW[b_w(16, ck, r1)] = pk(acc[mt][nt][2] + bb.x, acc[mt][nt][3] + bb.y);
            }
        }
    }
    __syncthreads();

    // ===== Phase 2: scores = Q @ K^T  (8 ksteps, N=128; warp tile 32x32) =====
#pragma unroll
    for (int mt = 0; mt < 2; mt++)
#pragma unroll
        for (int nt = 0; nt < 4; nt++)
#pragma unroll
            for (int e = 0; e < 4; e++) acc[mt][nt][e] = 0.f;
#pragma unroll
    for (int s = 0; s < 8; s++)
        step16<4>(acc, QW + wm * 2048 + s * 256 + lane * 4,
                  KtW + s * 1024 + wn * 256 + lane * 2);

    // ===== softmax (no max pass: |score| << 88, exp safe) -> attn-pack =====
    {
        const float fa = __ldg(alpha_p);
        const float invs = 0.08838834764831845f;
#pragma unroll
        for (int mt = 0; mt < 2; mt++)
#pragma unroll
            for (int h = 0; h < 2; h++) {
                const int r = mrow + mt * 16 + g + h * 8;
                float s = 0.f;
#pragma unroll
                for (int nt = 0; nt < 4; nt++) {
                    const int col = ncol2 + nt * 8 + 2 * t;
                    float2 av = __ldg((const float2*)&adj[r * 128 + col]);
                    float p0 = __expf(acc[mt][nt][h * 2 + 0] * invs + fa * fmaxf(av.x, 0.f));
                    float p1 = __expf(acc[mt][nt][h * 2 + 1] * invs + fa * fmaxf(av.y, 0.f));
                    acc[mt][nt][h * 2 + 0] = p0;
                    acc[mt][nt][h * 2 + 1] = p1;
                    s += p0 + p1;
                }
                s += __shfl_xor_sync(0xffffffffu, s, 1);
                s += __shfl_xor_sync(0xffffffffu, s, 2);
                scr[r * 4 + wn] = s;
            }
        __syncthreads();
#pragma unroll
        for (int mt = 0; mt < 2; mt++)
#pragma unroll
            for (int h = 0; h < 2; h++) {
                const int r = mrow + mt * 16 + g + h * 8;
                const float inv = 1.f / (scr[r * 4] + scr[r * 4 + 1]
                                       + scr[r * 4 + 2] + scr[r * 4 + 3]);
#pragma unroll
                for (int nt = 0; nt < 4; nt++) {
                    const int col = ncol2 + nt * 8 + 2 * t;
                    QW[a_w(8, r, col)] = pk(acc[mt][nt][h * 2 + 0] * inv,
                                            acc[mt][nt][h * 2 + 1] * inv);
                }
            }
    }
    __syncthreads();   // attn visible before phase-3 reads

    // ===== Phase 3: ax = attn @ x  (4 chunks of 32 k-rows, double-buffered) =====
#pragma unroll
    for (int mt = 0; mt < 2; mt++)
#pragma unroll
        for (int nt = 0; nt < 8; nt++)
#pragma unroll
            for (int e = 0; e < 4; e++) acc[mt][nt][e] = 0.f;

#pragma unroll
    for (int j = 0; j < 2; j++) {   // stage chunk 0
        int idx = j * 512 + tid;
        int rp = idx >> 6, c4 = (idx & 63) << 2;
        float4 va = __ldg((const float4*)(xb + (2 * rp) * 256 + c4));
        float4 vb = __ldg((const float4*)(xb + (2 * rp + 1) * 256 + c4));
        const int sl = rp >> 3, tt = rp & 3, hi = (rp >> 2) & 1;
        const float ax4[4] = {va.x, va.y, va.z, va.w};
        const float bx4[4] = {vb.x, vb.y, vb.z, vb.w};
#pragma unroll
        for (int i = 0; i < 4; i++) {
            int n = c4 + i;
            BB[((sl * 32 + (n >> 3)) * 32 + (n & 7) * 4 + tt) * 2 + hi] = pk(ax4[i], bx4[i]);
        }
    }
    __syncthreads();

    for (int c = 0; c < 4; c++) {
        if (c < 3) {
            uint32_t* buf = BB + ((c + 1) & 1) * 4096;
            const float* xs = xb + (c + 1) * 32 * 256;
#pragma unroll
            for (int j = 0; j < 2; j++) {
                int idx = j * 512 + tid;
                int rp = idx >> 6, c4 = (idx & 63) << 2;
                float4 va = __ldg((const float4*)(xs + (2 * rp) * 256 + c4));
                float4 vb = __ldg((const float4*)(xs + (2 * rp + 1) * 256 + c4));
                const int sl = rp >> 3, tt = rp & 3, hi = (rp >> 2) & 1;
                const float ax4[4] = {va.x, va.y, va.z, va.w};
                const float bx4[4] = {vb.x, vb.y, vb.z, vb.w};
#pragma unroll
                for (int i = 0; i < 4; i++) {
                    int n = c4 + i;
                    buf[((sl * 32 + (n >> 3)) * 32 + (n & 7) * 4 + tt) * 2 + hi] = pk(ax4[i], bx4[i]);
                }
            }
        }
        uint32_t* cur = BB + (c & 1) * 4096;
#pragma unroll
        for (int sl = 0; sl < 2; sl++)
            step16<8>(acc, QW + wm * 2048 + (c * 2 + sl) * 256 + lane * 4,
                      cur + sl * 2048 + wn * 512 + lane * 2);
        __syncthreads();
    }

    // prefetch first two weight double-chunks of phase 4 (BB free after final barrier)
    ISSUE_W2(0, g_WctPh);
    ISSUE_W2(1, g_WctPh);

    // epilogue: ax-pack (S=16) into A1 (attn/Kt dead)
#pragma unroll
    for (int nt = 0; nt < 8; nt++) {
        const int n = ncol + nt * 8 + 2 * t;
#pragma unroll
        for (int mt = 0; mt < 2; mt++) {
            const int r0 = mrow + mt * 16 + g, r1 = r0 + 8;
            A1[a_w(16, r0, n)] = pk(acc[mt][nt][0], acc[mt][nt][1]);
            A1[a_w(16, r1, n)] = pk(acc[mt][nt][2], acc[mt][nt][3]);
        }
    }
    __syncthreads();

    // ===== Phase 4: z = ax @ Wc^T  (8 double-ksteps, 8 barriers) =====
#pragma unroll
    for (int mt = 0; mt < 2; mt++)
#pragma unroll
        for (int nt = 0; nt < 8; nt++)
#pragma unroll
            for (int e = 0; e < 4; e++) acc[mt][nt][e] = 0.f;

    for (int cc = 0; cc < 8; cc++) {
        ISSUE_W2(cc + 2, g_WctPh);
        CP_WAIT2();
        __syncthreads();
#pragma unroll
        for (int sl = 0; sl < 2; sl++)
            step16<8>(acc, A1 + wm * 4096 + (2 * cc + sl) * 256 + lane * 4,
                      BB + (cc & 3) * 4096 + sl * 2048 + wn * 512 + lane * 2);
    }

    // ===== LN epilogue: h = relu(z + bc) + x; LayerNorm over C; store =====
#pragma unroll
    for (int mt = 0; mt < 2; mt++)
#pragma unroll
        for (int h = 0; h < 2; h++) {
            const int r = mrow + mt * 16 + g + h * 8;
            float s1 = 0.f, s2 = 0.f;
#pragma unroll
            for (int nt = 0; nt < 8; nt++) {
                const int n = ncol + nt * 8 + 2 * t;
                float2 bc2 = __ldg((const float2*)&g_bc[n]);
                float2 xv = __ldg((const float2*)&xb[r * 256 + n]);
                float h0 = fmaxf(acc[mt][nt][h * 2 + 0] + bc2.x, 0.f) + xv.x;
                float h1 = fmaxf(acc[mt][nt][h * 2 + 1] + bc2.y, 0.f) + xv.y;
                acc[mt][nt][h * 2 + 0] = h0;
                acc[mt][nt][h * 2 + 1] = h1;
                s1 += h0 + h1;
                s2 += h0 * h0 + h1 * h1;
            }
            s1 += __shfl_xor_sync(0xffffffffu, s1, 1);
            s1 += __shfl_xor_sync(0xffffffffu, s1, 2);
            s2 += __shfl_xor_sync(0xffffffffu, s2, 1);
            s2 += __shfl_xor_sync(0xffffffffu, s2, 2);
            scr[r * 4 + wn] = s1;
            scr[512 + r * 4 + wn] = s2;
        }
    __syncthreads();
    float* ob = out + (size_t)b * (NF * CC);
#pragma unroll
    for (int mt = 0; mt < 2; mt++)
#pragma unroll
        for (int h = 0; h < 2; h++) {
            const int r = mrow + mt * 16 + g + h * 8;
            const float S  = scr[r * 4] + scr[r * 4 + 1] + scr[r * 4 + 2] + scr[r * 4 + 3];
            const float Q2 = scr[512 + r * 4] + scr[512 + r * 4 + 1]
                           + scr[512 + r * 4 + 2] + scr[512 + r * 4 + 3];
            const float mean = S * (1.f / 256.f);
            const float rstd = rsqrtf(Q2 * (1.f / 256.f) - mean * mean + 1e-5f);
#pragma unroll
            for (int nt = 0; nt < 8; nt++) {
                const int n = ncol + nt * 8 + 2 * t;
                float2 g2 = __ldg((const float2*)&gamma[n]);
                float2 b2 = __ldg((const float2*)&beta[n]);
                float2 o;
                o.x = (acc[mt][nt][h * 2 + 0] - mean) * rstd * g2.x + b2.x;
                o.y = (acc[mt][nt][h * 2 + 1] - mean) * rstd * g2.y + b2.y;
                *(float2*)(ob + r * 256 + n) = o;
            }
        }
#undef ISSUE_W2
}

extern "C" void kernel_launch(void* const* d_in, const int* in_sizes, int n_in,
                              void* d_out, int out_size)
{
    (void)in_sizes; (void)n_in; (void)out_size;
    const float* x     = (const float*)d_in[0];
    const float* ee    = (const float*)d_in[1];
    const float* adj   = (const float*)d_in[2];
    const float* alpha = (const float*)d_in[3];
    const float* Wq    = (const float*)d_in[4];
    const float* bq    = (const float*)d_in[5];
    const float* Wk    = (const float*)d_in[6];
    const float* bk    = (const float*)d_in[7];
    const float* Wv    = (const float*)d_in[8];
    const float* bv    = (const float*)d_in[9];
    const float* Wg    = (const float*)d_in[10];
    const float* bg    = (const float*)d_in[11];
    const float* gamma = (const float*)d_in[12];
    const float* beta  = (const float*)d_in[13];
    float* out = (float*)d_out;

    cudaFuncSetAttribute(fused_kernel, cudaFuncAttributeMaxDynamicSharedMemorySize, SMEM_BYTES);
    prep_all<<<32, 256>>>(Wq, Wk, Wg, Wv, bv, bg);
    fused_kernel<<<BT, 512, SMEM_BYTES>>>(x, ee, adj, alpha, bq, bk, gamma, beta, out);
}